// round 1
// baseline (speedup 1.0000x reference)
#include <cuda_runtime.h>
#include <math.h>

// Problem constants
#define BB 128
#define SS 256
#define EE 825
#define HH 600
#define G4 2400      // 4*H
#define MROWS 32768  // B*S
#define CTX_STRIDE 1200  // 2*H
#define OUT_BLK 153600   // 128*1200

// GEMM tiling
#define BM 64
#define BN 64
#define BK 16
#define TM 4
#define TN 4

// Scratch (device globals — no runtime allocation allowed)
__device__ float g_buf1[MROWS * EE];            // 108 MB
__device__ float g_buf2[MROWS * EE];            // 108 MB
__device__ float g_gates[157286400];            // 32768*4800, 629 MB
__device__ float g_gt[2 * BB * G4];             // per-step gates
__device__ float g_h[2 * BB * HH];
__device__ float g_c[2 * BB * HH];

__device__ __forceinline__ float sigm(float x) {
    return 1.0f / (1.0f + expf(-x));
}

// ---------------------------------------------------------------------------
// init: copy h0/c0 into state buffers
// ---------------------------------------------------------------------------
__global__ void init_kernel(const float* __restrict__ h0, const float* __restrict__ c0) {
    int idx = blockIdx.x * blockDim.x + threadIdx.x;
    if (idx < 2 * BB * HH) {
        g_h[idx] = h0[idx];
        g_c[idx] = c0[idx];
    }
}

// ---------------------------------------------------------------------------
// Highway layer: Y = sig(X@Wg^T+bg) * relu(X@Wn^T+bn) + (1-sig)*(X@Wl^T+bl)
// X: M x K, W*: N x K, M=32768, N=K=825. Fused 3-matrix GEMM.
// ---------------------------------------------------------------------------
__global__ void highway_kernel(const float* __restrict__ X,
                               const float* __restrict__ Wg, const float* __restrict__ bgp,
                               const float* __restrict__ Wn, const float* __restrict__ bnp,
                               const float* __restrict__ Wl, const float* __restrict__ blp,
                               float* __restrict__ Y, int M, int N, int K) {
    __shared__ float As[BK][BM];
    __shared__ float Bg[BK][BN];
    __shared__ float Bn[BK][BN];
    __shared__ float Bl[BK][BN];

    const int m0 = blockIdx.x * BM;
    const int n0 = blockIdx.y * BN;
    const int tid = threadIdx.x;
    const int tr = tid >> 4;        // 0..15
    const int tc = tid & 15;        // 0..15
    const int lar = tid >> 2;       // 0..63
    const int lak = (tid & 3) * 4;  // 0,4,8,12

    float accG[TM][TN] = {};
    float accN[TM][TN] = {};
    float accL[TM][TN] = {};

    for (int k0 = 0; k0 < K; k0 += BK) {
        {
            int grow = m0 + lar;
            #pragma unroll
            for (int q = 0; q < 4; q++) {
                int gk = k0 + lak + q;
                float v = 0.f;
                if (gk < K) v = X[(long)grow * K + gk];
                As[lak + q][lar] = v;
            }
        }
        {
            int gn = n0 + lar;
            #pragma unroll
            for (int q = 0; q < 4; q++) {
                int gk = k0 + lak + q;
                float vg = 0.f, vn = 0.f, vl = 0.f;
                if (gn < N && gk < K) {
                    long off = (long)gn * K + gk;
                    vg = Wg[off]; vn = Wn[off]; vl = Wl[off];
                }
                Bg[lak + q][lar] = vg;
                Bn[lak + q][lar] = vn;
                Bl[lak + q][lar] = vl;
            }
        }
        __syncthreads();
        #pragma unroll
        for (int k = 0; k < BK; k++) {
            float am[TM], bgv[TN], bnv[TN], blv[TN];
            #pragma unroll
            for (int i = 0; i < TM; i++) am[i] = As[k][tr * TM + i];
            #pragma unroll
            for (int j = 0; j < TN; j++) {
                bgv[j] = Bg[k][tc * TN + j];
                bnv[j] = Bn[k][tc * TN + j];
                blv[j] = Bl[k][tc * TN + j];
            }
            #pragma unroll
            for (int i = 0; i < TM; i++)
                #pragma unroll
                for (int j = 0; j < TN; j++) {
                    accG[i][j] += am[i] * bgv[j];
                    accN[i][j] += am[i] * bnv[j];
                    accL[i][j] += am[i] * blv[j];
                }
        }
        __syncthreads();
    }

    #pragma unroll
    for (int i = 0; i < TM; i++) {
        int grow = m0 + tr * TM + i;
        #pragma unroll
        for (int j = 0; j < TN; j++) {
            int gn = n0 + tc * TN + j;
            if (gn < N) {
                float gate = sigm(accG[i][j] + bgp[gn]);
                float nl   = fmaxf(accN[i][j] + bnp[gn], 0.f);
                float ln   = accL[i][j] + blp[gn];
                Y[(long)grow * N + gn] = gate * nl + (1.f - gate) * ln;
            }
        }
    }
}

// ---------------------------------------------------------------------------
// Input-gate precompute: C[r][n] = xh[r] . W_ih_flat[n] + b_ih[n] + b_hh[n]
// M=32768, N=4800 (both dirs concatenated), K=825
// ---------------------------------------------------------------------------
__global__ void gatesx_kernel(const float* __restrict__ A, const float* __restrict__ Bmat,
                              const float* __restrict__ bias1, const float* __restrict__ bias2,
                              float* __restrict__ C, int M, int N, int K) {
    __shared__ float As[BK][BM];
    __shared__ float Bs[BK][BN];

    const int m0 = blockIdx.x * BM;
    const int n0 = blockIdx.y * BN;
    const int tid = threadIdx.x;
    const int tr = tid >> 4;
    const int tc = tid & 15;
    const int lar = tid >> 2;
    const int lak = (tid & 3) * 4;

    float acc[TM][TN] = {};

    for (int k0 = 0; k0 < K; k0 += BK) {
        {
            int grow = m0 + lar;
            #pragma unroll
            for (int q = 0; q < 4; q++) {
                int gk = k0 + lak + q;
                float v = 0.f;
                if (gk < K) v = A[(long)grow * K + gk];
                As[lak + q][lar] = v;
            }
        }
        {
            int gn = n0 + lar;
            #pragma unroll
            for (int q = 0; q < 4; q++) {
                int gk = k0 + lak + q;
                float v = 0.f;
                if (gk < K) v = Bmat[(long)gn * K + gk];
                Bs[lak + q][lar] = v;
            }
        }
        __syncthreads();
        #pragma unroll
        for (int k = 0; k < BK; k++) {
            float am[TM], bv[TN];
            #pragma unroll
            for (int i = 0; i < TM; i++) am[i] = As[k][tr * TM + i];
            #pragma unroll
            for (int j = 0; j < TN; j++) bv[j] = Bs[k][tc * TN + j];
            #pragma unroll
            for (int i = 0; i < TM; i++)
                #pragma unroll
                for (int j = 0; j < TN; j++)
                    acc[i][j] += am[i] * bv[j];
        }
        __syncthreads();
    }

    #pragma unroll
    for (int i = 0; i < TM; i++) {
        int grow = m0 + tr * TM + i;
        #pragma unroll
        for (int j = 0; j < TN; j++) {
            int gn = n0 + tc * TN + j;
            C[(long)grow * N + gn] = acc[i][j] + bias1[gn] + bias2[gn];
        }
    }
}

// ---------------------------------------------------------------------------
// Per-step recurrent GEMM: gt[d][b][g] = h[d][b] . W_hh[d][g] + gates_x[b,t,d,g]
// M=128, N=2400, K=600; blockIdx.z = direction
// ---------------------------------------------------------------------------
__global__ void step_gemm_kernel(const float* __restrict__ Whh, int t) {
    __shared__ float As[BK][BM];
    __shared__ float Bs[BK][BN];

    const int d = blockIdx.z;
    const float* A = g_h + d * BB * HH;
    const float* Bmat = Whh + (long)d * G4 * HH;

    const int M = BB, N = G4, K = HH;
    const int m0 = blockIdx.x * BM;
    const int n0 = blockIdx.y * BN;
    const int tid = threadIdx.x;
    const int tr = tid >> 4;
    const int tc = tid & 15;
    const int lar = tid >> 2;
    const int lak = (tid & 3) * 4;

    float acc[TM][TN] = {};

    for (int k0 = 0; k0 < K; k0 += BK) {
        {
            int grow = m0 + lar;
            #pragma unroll
            for (int q = 0; q < 4; q++) {
                int gk = k0 + lak + q;
                float v = 0.f;
                if (grow < M && gk < K) v = A[(long)grow * K + gk];
                As[lak + q][lar] = v;
            }
        }
        {
            int gn = n0 + lar;
            #pragma unroll
            for (int q = 0; q < 4; q++) {
                int gk = k0 + lak + q;
                float v = 0.f;
                if (gn < N && gk < K) v = Bmat[(long)gn * K + gk];
                Bs[lak + q][lar] = v;
            }
        }
        __syncthreads();
        #pragma unroll
        for (int k = 0; k < BK; k++) {
            float am[TM], bv[TN];
            #pragma unroll
            for (int i = 0; i < TM; i++) am[i] = As[k][tr * TM + i];
            #pragma unroll
            for (int j = 0; j < TN; j++) bv[j] = Bs[k][tc * TN + j];
            #pragma unroll
            for (int i = 0; i < TM; i++)
                #pragma unroll
                for (int j = 0; j < TN; j++)
                    acc[i][j] += am[i] * bv[j];
        }
        __syncthreads();
    }

    #pragma unroll
    for (int i = 0; i < TM; i++) {
        int b = m0 + tr * TM + i;
        if (b >= M) continue;
        #pragma unroll
        for (int j = 0; j < TN; j++) {
            int gn = n0 + tc * TN + j;
            if (gn >= N) continue;
            float gx = g_gates[((long)b * SS + t) * 4800 + d * G4 + gn];
            g_gt[((long)d * BB + b) * G4 + gn] = acc[i][j] + gx;
        }
    }
}

// ---------------------------------------------------------------------------
// LSTM cell elementwise: updates g_h, g_c in place; writes context[t]
// ---------------------------------------------------------------------------
__global__ void lstm_cell_kernel(float* __restrict__ context, int t) {
    int idx = blockIdx.x * blockDim.x + threadIdx.x;
    if (idx >= 2 * BB * HH) return;
    int hh = idx % HH;
    int b = (idx / HH) % BB;
    int d = idx / (HH * BB);
    const float* g = g_gt + ((long)d * BB + b) * G4;
    float gi = g[hh];
    float gf = g[HH + hh];
    float gg = g[2 * HH + hh];
    float go = g[3 * HH + hh];
    float cold = g_c[idx];
    float cn = sigm(gf) * cold + sigm(gi) * tanhf(gg);
    float hn = sigm(go) * tanhf(cn);
    g_c[idx] = cn;
    g_h[idx] = hn;
    context[(long)t * OUT_BLK + (long)b * CTX_STRIDE + d * HH + hh] = hn;
}

// ---------------------------------------------------------------------------
// Finalize: encoder_outputs = final_state = context[S-1]; h_n, c_n
// ---------------------------------------------------------------------------
__global__ void finalize_kernel(float* __restrict__ out) {
    int idx = blockIdx.x * blockDim.x + threadIdx.x;
    if (idx >= OUT_BLK) return;
    const float* ctx_last = out + 4L * OUT_BLK + (long)(SS - 1) * OUT_BLK;
    float v = ctx_last[idx];
    out[idx] = v;                 // encoder_outputs (B,1,1200)
    out[OUT_BLK + idx] = v;       // final_state (B,1200)
    out[2L * OUT_BLK + idx] = g_h[idx];  // h_n (2,B,600)
    out[3L * OUT_BLK + idx] = g_c[idx];  // c_n (2,B,600)
}

// ---------------------------------------------------------------------------
extern "C" void kernel_launch(void* const* d_in, const int* in_sizes, int n_in,
                              void* d_out, int out_size) {
    const float* x      = (const float*)d_in[0];
    const float* h0     = (const float*)d_in[1];
    const float* c0     = (const float*)d_in[2];
    const float* hw_Wg  = (const float*)d_in[3];
    const float* hw_bg  = (const float*)d_in[4];
    const float* hw_Wn  = (const float*)d_in[5];
    const float* hw_bn  = (const float*)d_in[6];
    const float* hw_Wl  = (const float*)d_in[7];
    const float* hw_bl  = (const float*)d_in[8];
    const float* W_ih   = (const float*)d_in[9];
    const float* W_hh   = (const float*)d_in[10];
    const float* b_ih   = (const float*)d_in[11];
    const float* b_hh   = (const float*)d_in[12];
    float* out = (float*)d_out;

    float *p_buf1, *p_buf2, *p_gates;
    cudaGetSymbolAddress((void**)&p_buf1, g_buf1);
    cudaGetSymbolAddress((void**)&p_buf2, g_buf2);
    cudaGetSymbolAddress((void**)&p_gates, g_gates);

    dim3 thr(256);

    init_kernel<<<(2 * BB * HH + 255) / 256, 256>>>(h0, c0);

    // Highway layers (M=32768, N=K=825)
    dim3 gHW((MROWS + BM - 1) / BM, (EE + BN - 1) / BN);
    highway_kernel<<<gHW, thr>>>(x, hw_Wg, hw_bg, hw_Wn, hw_bn, hw_Wl, hw_bl,
                                 p_buf1, MROWS, EE, EE);
    highway_kernel<<<gHW, thr>>>(p_buf1,
                                 hw_Wg + EE * EE, hw_bg + EE,
                                 hw_Wn + EE * EE, hw_bn + EE,
                                 hw_Wl + EE * EE, hw_bl + EE,
                                 p_buf2, MROWS, EE, EE);

    // Input-gate precompute for both directions: (32768 x 4800)
    dim3 gGX((MROWS + BM - 1) / BM, (4800 + BN - 1) / BN);
    gatesx_kernel<<<gGX, thr>>>(p_buf2, W_ih, b_ih, b_hh, p_gates, MROWS, 4800, EE);

    // Sequential recurrence
    dim3 gST((BB + BM - 1) / BM, (G4 + BN - 1) / BN, 2);
    float* context = out + 4L * OUT_BLK;
    for (int t = 0; t < SS; t++) {
        step_gemm_kernel<<<gST, thr>>>(W_hh, t);
        lstm_cell_kernel<<<(2 * BB * HH + 255) / 256, 256>>>(context, t);
    }

    finalize_kernel<<<(OUT_BLK + 255) / 256, 256>>>(out);
}

// round 4
// speedup vs baseline: 2.0633x; 2.0633x over previous
#include <cuda_runtime.h>
#include <cuda_bf16.h>
#include <mma.h>
#include <math.h>
#include <stdint.h>

using namespace nvcuda;

// Problem constants
#define BB 128
#define SS 256
#define EE 825
#define KP 832            // E padded to 26*32
#define HH 600
#define HHP 608           // H padded to 19*32
#define G4 2400           // 4*H
#define G4P 2432          // padded to 76*32 (and 19*128)
#define MROWS 32768       // B*S
#define CTX_STRIDE 1200   // 2*H
#define OUT_BLK 153600    // 128*1200
#define NIH 4800          // 2*4*H
#define NIH_PAD 4864      // 38*128
#define NHW_PAD 896       // 7*128

// ---------------------------------------------------------------------------
// Scratch (device globals — no runtime allocation allowed)
// ---------------------------------------------------------------------------
__device__ float g_gates[159383552];               // 32768*4864 (also highway raw scratch)
__device__ __nv_bfloat16 g_Ahi[MROWS * KP];
__device__ __nv_bfloat16 g_Alo[MROWS * KP];
__device__ __nv_bfloat16 g_Bhi[NIH_PAD * KP];
__device__ __nv_bfloat16 g_Blo[NIH_PAD * KP];
__device__ __nv_bfloat16 g_Whi[2 * G4P * HHP];
__device__ __nv_bfloat16 g_Wlo[2 * G4P * HHP];
__device__ __nv_bfloat16 g_hbf_hi[2 * BB * HHP];
__device__ __nv_bfloat16 g_hbf_lo[2 * BB * HHP];
__device__ float g_bias_sum[NIH];
__device__ float g_gt[2 * BB * G4P];
__device__ float g_h[2 * BB * HH];
__device__ float g_c[2 * BB * HH];

__device__ __forceinline__ float sigm(float x) { return 1.0f / (1.0f + expf(-x)); }

// ---------------------------------------------------------------------------
// Big GEMM via wmma bf16 split precision.
// C[m0..+128, n0..+128] = A@B^T with A,B split hi/lo (hi*hi + hi*lo + lo*hi),
// fp32 accumulate. A: [M, KP] row-major, B: [Npad, KP] row-major.
// ---------------------------------------------------------------------------
__global__ void __launch_bounds__(256) gemm_wmma_kernel(
        const __nv_bfloat16* __restrict__ Ahi, const __nv_bfloat16* __restrict__ Alo,
        const __nv_bfloat16* __restrict__ Bhi, const __nv_bfloat16* __restrict__ Blo,
        float* __restrict__ C, int ldc) {
    __shared__ __nv_bfloat16 sAh[128][40];
    __shared__ __nv_bfloat16 sAl[128][40];
    __shared__ __nv_bfloat16 sBh[128][40];
    __shared__ __nv_bfloat16 sBl[128][40];

    const int tid = threadIdx.x;
    const int wid = tid >> 5;
    const int wm = wid >> 1;        // 0..3 : 32-row slice
    const int wn = wid & 1;         // 0..1 : 64-col slice
    const size_t m0 = (size_t)blockIdx.x * 128;
    const size_t n0 = (size_t)blockIdx.y * 128;

    wmma::fragment<wmma::accumulator, 16, 16, 16, float> acc[2][4];
    #pragma unroll
    for (int i = 0; i < 2; i++)
        #pragma unroll
        for (int j = 0; j < 4; j++)
            wmma::fill_fragment(acc[i][j], 0.0f);

    for (int kb = 0; kb < KP / 32; kb++) {
        #pragma unroll
        for (int r = 0; r < 2; r++) {
            int idx = tid + r * 256;       // 0..511
            int row = idx >> 2, q = idx & 3;
            size_t ga = (m0 + row) * KP + kb * 32 + q * 8;
            size_t gb = (n0 + row) * KP + kb * 32 + q * 8;
            *(uint4*)&sAh[row][q * 8] = *(const uint4*)&Ahi[ga];
            *(uint4*)&sAl[row][q * 8] = *(const uint4*)&Alo[ga];
            *(uint4*)&sBh[row][q * 8] = *(const uint4*)&Bhi[gb];
            *(uint4*)&sBl[row][q * 8] = *(const uint4*)&Blo[gb];
        }
        __syncthreads();

        #pragma unroll
        for (int ks = 0; ks < 2; ks++) {
            wmma::fragment<wmma::matrix_a, 16, 16, 16, __nv_bfloat16, wmma::row_major> ah[2], al[2];
            wmma::fragment<wmma::matrix_b, 16, 16, 16, __nv_bfloat16, wmma::col_major> bh[4], bl[4];
            #pragma unroll
            for (int i = 0; i < 2; i++) {
                wmma::load_matrix_sync(ah[i], &sAh[wm * 32 + i * 16][ks * 16], 40);
                wmma::load_matrix_sync(al[i], &sAl[wm * 32 + i * 16][ks * 16], 40);
            }
            #pragma unroll
            for (int j = 0; j < 4; j++) {
                wmma::load_matrix_sync(bh[j], &sBh[wn * 64 + j * 16][ks * 16], 40);
                wmma::load_matrix_sync(bl[j], &sBl[wn * 64 + j * 16][ks * 16], 40);
            }
            #pragma unroll
            for (int i = 0; i < 2; i++)
                #pragma unroll
                for (int j = 0; j < 4; j++) {
                    wmma::mma_sync(acc[i][j], ah[i], bh[j], acc[i][j]);
                    wmma::mma_sync(acc[i][j], ah[i], bl[j], acc[i][j]);
                    wmma::mma_sync(acc[i][j], al[i], bh[j], acc[i][j]);
                }
        }
        __syncthreads();
    }

    #pragma unroll
    for (int i = 0; i < 2; i++)
        #pragma unroll
        for (int j = 0; j < 4; j++)
            wmma::store_matrix_sync(&C[(m0 + wm * 32 + i * 16) * ldc + n0 + wn * 64 + j * 16],
                                    acc[i][j], ldc, wmma::mem_row_major);
}

// ---------------------------------------------------------------------------
// Recurrent step GEMM via wmma: g_gt[d] = h[d] @ W_hh[d]^T  (raw, no bias)
// A = g_hbf (128 x HHP split bf16), B = g_W (G4P x HHP split bf16)
// CTA: 128 x 32 tile, 4 warps, warp = 32 x 32. grid (G4P/32, 2)
// ---------------------------------------------------------------------------
__global__ void __launch_bounds__(128) step_wmma_kernel() {
    __shared__ __nv_bfloat16 sAh[128][40];
    __shared__ __nv_bfloat16 sAl[128][40];
    __shared__ __nv_bfloat16 sBh[32][40];
    __shared__ __nv_bfloat16 sBl[32][40];

    const int tid = threadIdx.x;
    const int wid = tid >> 5;       // 0..3 : M slice
    const int d = blockIdx.y;
    const size_t n0 = (size_t)blockIdx.x * 32;

    const __nv_bfloat16* Ahi = g_hbf_hi + (size_t)d * BB * HHP;
    const __nv_bfloat16* Alo = g_hbf_lo + (size_t)d * BB * HHP;
    const __nv_bfloat16* Bhi = g_Whi + (size_t)d * G4P * HHP;
    const __nv_bfloat16* Blo = g_Wlo + (size_t)d * G4P * HHP;

    wmma::fragment<wmma::accumulator, 16, 16, 16, float> acc[2][2];
    #pragma unroll
    for (int i = 0; i < 2; i++)
        #pragma unroll
        for (int j = 0; j < 2; j++)
            wmma::fill_fragment(acc[i][j], 0.0f);

    for (int kb = 0; kb < HHP / 32; kb++) {
        #pragma unroll
        for (int r = 0; r < 4; r++) {
            int idx = tid + r * 128;        // 0..511
            int row = idx >> 2, q = idx & 3;
            size_t ga = (size_t)row * HHP + kb * 32 + q * 8;
            *(uint4*)&sAh[row][q * 8] = *(const uint4*)&Ahi[ga];
            *(uint4*)&sAl[row][q * 8] = *(const uint4*)&Alo[ga];
        }
        {
            int row = tid >> 2, q = tid & 3;
            size_t gb = (n0 + row) * HHP + kb * 32 + q * 8;
            *(uint4*)&sBh[row][q * 8] = *(const uint4*)&Bhi[gb];
            *(uint4*)&sBl[row][q * 8] = *(const uint4*)&Blo[gb];
        }
        __syncthreads();

        #pragma unroll
        for (int ks = 0; ks < 2; ks++) {
            wmma::fragment<wmma::matrix_a, 16, 16, 16, __nv_bfloat16, wmma::row_major> ah[2], al[2];
            wmma::fragment<wmma::matrix_b, 16, 16, 16, __nv_bfloat16, wmma::col_major> bh[2], bl[2];
            #pragma unroll
            for (int i = 0; i < 2; i++) {
                wmma::load_matrix_sync(ah[i], &sAh[wid * 32 + i * 16][ks * 16], 40);
                wmma::load_matrix_sync(al[i], &sAl[wid * 32 + i * 16][ks * 16], 40);
            }
            #pragma unroll
            for (int j = 0; j < 2; j++) {
                wmma::load_matrix_sync(bh[j], &sBh[j * 16][ks * 16], 40);
                wmma::load_matrix_sync(bl[j], &sBl[j * 16][ks * 16], 40);
            }
            #pragma unroll
            for (int i = 0; i < 2; i++)
                #pragma unroll
                for (int j = 0; j < 2; j++) {
                    wmma::mma_sync(acc[i][j], ah[i], bh[j], acc[i][j]);
                    wmma::mma_sync(acc[i][j], ah[i], bl[j], acc[i][j]);
                    wmma::mma_sync(acc[i][j], al[i], bh[j], acc[i][j]);
                }
        }
        __syncthreads();
    }

    #pragma unroll
    for (int i = 0; i < 2; i++)
        #pragma unroll
        for (int j = 0; j < 2; j++)
            wmma::store_matrix_sync(&g_gt[(size_t)(d * BB + wid * 32 + i * 16) * G4P + n0 + j * 16],
                                    acc[i][j], G4P, wmma::mem_row_major);
}

// ---------------------------------------------------------------------------
// Conversions / elementwise
// ---------------------------------------------------------------------------
__global__ void init_kernel(const float* __restrict__ h0, const float* __restrict__ c0,
                            const float* __restrict__ b_ih, const float* __restrict__ b_hh) {
    int idx = blockIdx.x * blockDim.x + threadIdx.x;
    if (idx < 2 * BB * HH) { g_h[idx] = h0[idx]; g_c[idx] = c0[idx]; }
    if (idx < NIH) g_bias_sum[idx] = b_ih[idx] + b_hh[idx];
    if (idx < 2 * BB * HHP) {
        int hh = idx % HHP;
        int db = idx / HHP;
        float v = (hh < HH) ? h0[db * HH + hh] : 0.0f;
        __nv_bfloat16 hi = __float2bfloat16(v);
        g_hbf_hi[idx] = hi;
        g_hbf_lo[idx] = __float2bfloat16(v - __bfloat162float(hi));
    }
}

// x fp32 (stride EE) -> split bf16 (stride KP, zero-padded)
__global__ void convA_kernel(const float* __restrict__ src) {
    int idx = blockIdx.x * blockDim.x + threadIdx.x;
    if (idx >= MROWS * KP) return;
    int col = idx % KP, row = idx / KP;
    float v = (col < EE) ? src[(size_t)row * EE + col] : 0.0f;
    __nv_bfloat16 hi = __float2bfloat16(v);
    g_Ahi[idx] = hi;
    g_Alo[idx] = __float2bfloat16(v - __bfloat162float(hi));
}

// weight (Nreal x EE) -> split bf16 (Npad x KP)
__global__ void convW_kernel(const float* __restrict__ src, int Nreal, int Npad) {
    int idx = blockIdx.x * blockDim.x + threadIdx.x;
    if (idx >= Npad * KP) return;
    int col = idx % KP, row = idx / KP;
    float v = (row < Nreal && col < EE) ? src[(size_t)row * EE + col] : 0.0f;
    __nv_bfloat16 hi = __float2bfloat16(v);
    g_Bhi[idx] = hi;
    g_Blo[idx] = __float2bfloat16(v - __bfloat162float(hi));
}

// W_hh (2 x G4 x HH) -> split bf16 (2 x G4P x HHP)
__global__ void convWhh_kernel(const float* __restrict__ W) {
    int idx = blockIdx.x * blockDim.x + threadIdx.x;
    if (idx >= 2 * G4P * HHP) return;
    int col = idx % HHP;
    int rowd = idx / HHP;
    int row = rowd % G4P;
    int d = rowd / G4P;
    float v = (row < G4 && col < HH) ? W[((size_t)d * G4 + row) * HH + col] : 0.0f;
    __nv_bfloat16 hi = __float2bfloat16(v);
    g_Whi[idx] = hi;
    g_Wlo[idx] = __float2bfloat16(v - __bfloat162float(hi));
}

// highway combine: y = sig(G+bg)*relu(N+bn) + (1-sig)*(L+bl); emit split bf16
__global__ void combine_kernel(const float* __restrict__ rawG, const float* __restrict__ rawN,
                               const float* __restrict__ rawL,
                               const float* __restrict__ bg, const float* __restrict__ bn,
                               const float* __restrict__ bl) {
    int idx = blockIdx.x * blockDim.x + threadIdx.x;
    if (idx >= MROWS * KP) return;
    int col = idx % KP, row = idx / KP;
    float y = 0.0f;
    if (col < EE) {
        size_t r = (size_t)row * NHW_PAD + col;
        float gate = sigm(rawG[r] + bg[col]);
        float nl   = fmaxf(rawN[r] + bn[col], 0.0f);
        float ln   = rawL[r] + bl[col];
        y = gate * nl + (1.0f - gate) * ln;
    }
    __nv_bfloat16 hi = __float2bfloat16(y);
    g_Ahi[idx] = hi;
    g_Alo[idx] = __float2bfloat16(y - __bfloat162float(hi));
}

// LSTM cell: gates = g_gt (recurrent) + g_gates (input part) + bias
__global__ void lstm_cell_kernel(float* __restrict__ context, int t) {
    int idx = blockIdx.x * blockDim.x + threadIdx.x;
    if (idx >= 2 * BB * HH) return;
    int hh = idx % HH;
    int b = (idx / HH) % BB;
    int d = idx / (HH * BB);
    size_t gt = (size_t)(d * BB + b) * G4P;
    size_t gx = ((size_t)b * SS + t) * NIH_PAD + d * G4;
    int bi = d * G4;
    float gi = g_gt[gt + hh]            + g_gates[gx + hh]            + g_bias_sum[bi + hh];
    float gf = g_gt[gt + HH + hh]       + g_gates[gx + HH + hh]       + g_bias_sum[bi + HH + hh];
    float gg = g_gt[gt + 2 * HH + hh]   + g_gates[gx + 2 * HH + hh]   + g_bias_sum[bi + 2 * HH + hh];
    float go = g_gt[gt + 3 * HH + hh]   + g_gates[gx + 3 * HH + hh]   + g_bias_sum[bi + 3 * HH + hh];
    float cold = g_c[idx];
    float cn = sigm(gf) * cold + sigm(gi) * tanhf(gg);
    float hn = sigm(go) * tanhf(cn);
    g_c[idx] = cn;
    g_h[idx] = hn;
    int hb = (d * BB + b) * HHP + hh;
    __nv_bfloat16 hi = __float2bfloat16(hn);
    g_hbf_hi[hb] = hi;
    g_hbf_lo[hb] = __float2bfloat16(hn - __bfloat162float(hi));
    context[(size_t)t * OUT_BLK + (size_t)b * CTX_STRIDE + d * HH + hh] = hn;
}

__global__ void finalize_kernel(float* __restrict__ out) {
    int idx = blockIdx.x * blockDim.x + threadIdx.x;
    if (idx >= OUT_BLK) return;
    const float* ctx_last = out + 4L * OUT_BLK + (long)(SS - 1) * OUT_BLK;
    float v = ctx_last[idx];
    out[idx] = v;
    out[OUT_BLK + idx] = v;
    out[2L * OUT_BLK + idx] = g_h[idx];
    out[3L * OUT_BLK + idx] = g_c[idx];
}

// ---------------------------------------------------------------------------
extern "C" void kernel_launch(void* const* d_in, const int* in_sizes, int n_in,
                              void* d_out, int out_size) {
    const float* x      = (const float*)d_in[0];
    const float* h0     = (const float*)d_in[1];
    const float* c0     = (const float*)d_in[2];
    const float* hw_Wg  = (const float*)d_in[3];
    const float* hw_bg  = (const float*)d_in[4];
    const float* hw_Wn  = (const float*)d_in[5];
    const float* hw_bn  = (const float*)d_in[6];
    const float* hw_Wl  = (const float*)d_in[7];
    const float* hw_bl  = (const float*)d_in[8];
    const float* W_ih   = (const float*)d_in[9];
    const float* W_hh   = (const float*)d_in[10];
    const float* b_ih   = (const float*)d_in[11];
    const float* b_hh   = (const float*)d_in[12];
    float* out = (float*)d_out;

    float *p_gates;
    __nv_bfloat16 *p_Ahi, *p_Alo, *p_Bhi, *p_Blo;
    cudaGetSymbolAddress((void**)&p_gates, g_gates);
    cudaGetSymbolAddress((void**)&p_Ahi, g_Ahi);
    cudaGetSymbolAddress((void**)&p_Alo, g_Alo);
    cudaGetSymbolAddress((void**)&p_Bhi, g_Bhi);
    cudaGetSymbolAddress((void**)&p_Blo, g_Blo);

    init_kernel<<<(2 * BB * HHP + 255) / 256, 256>>>(h0, c0, b_ih, b_hh);

    // W_hh split conversion (independent, do early)
    convWhh_kernel<<<(2 * G4P * HHP + 255) / 256, 256>>>(W_hh);

    // x -> split bf16 activations
    convA_kernel<<<(MROWS * KP + 255) / 256, 256>>>(x);

    // Highway layers via wmma (raw G/N/L into g_gates scratch, stride NHW_PAD)
    float* raw[3] = { p_gates,
                      p_gates + (size_t)MROWS * NHW_PAD,
                      p_gates + 2 * (size_t)MROWS * NHW_PAD };
    const float* Ws[3] = { hw_Wg, hw_Wn, hw_Wl };
    dim3 gHW(MROWS / 128, NHW_PAD / 128);  // 256 x 7
    for (int l = 0; l < 2; l++) {
        for (int w = 0; w < 3; w++) {
            convW_kernel<<<(NHW_PAD * KP + 255) / 256, 256>>>(Ws[w] + (size_t)l * EE * EE, EE, NHW_PAD);
            gemm_wmma_kernel<<<gHW, 256>>>(p_Ahi, p_Alo, p_Bhi, p_Blo, raw[w], NHW_PAD);
        }
        combine_kernel<<<(MROWS * KP + 255) / 256, 256>>>(
            raw[0], raw[1], raw[2],
            hw_bg + l * EE, hw_bn + l * EE, hw_bl + l * EE);
    }

    // Input-gate precompute: (32768 x 4864) via wmma (raw, bias folded into cell)
    convW_kernel<<<(NIH_PAD * KP + 255) / 256, 256>>>(W_ih, NIH, NIH_PAD);
    dim3 gGX(MROWS / 128, NIH_PAD / 128);  // 256 x 38
    gemm_wmma_kernel<<<gGX, 256>>>(p_Ahi, p_Alo, p_Bhi, p_Blo, p_gates, NIH_PAD);

    // Sequential recurrence
    dim3 gST(G4P / 32, 2);  // 76 x 2
    float* context = out + 4L * OUT_BLK;
    for (int t = 0; t < SS; t++) {
        step_wmma_kernel<<<gST, 128>>>();
        lstm_cell_kernel<<<(2 * BB * HH + 255) / 256, 256>>>(context, t);
    }

    finalize_kernel<<<(OUT_BLK + 255) / 256, 256>>>(out);
}

// round 5
// speedup vs baseline: 2.7359x; 1.3259x over previous
#include <cuda_runtime.h>
#include <cuda_bf16.h>
#include <cuda_pipeline.h>
#include <mma.h>
#include <math.h>
#include <stdint.h>

using namespace nvcuda;

// Problem constants
#define BB 128
#define SS 256
#define EE 825
#define KP 832            // E padded to 26*32
#define HH 600
#define HHP 608           // H padded to 19*32
#define G4 2400           // 4*H
#define G4P 2432
#define MROWS 32768       // B*S
#define CTX_STRIDE 1200   // 2*H
#define OUT_BLK 153600    // 128*1200
#define NIH 4800          // 2*4*H
#define NIH_PAD 4864      // 38*128
#define NHW_PAD 896       // 7*128

// ---------------------------------------------------------------------------
// Scratch (device globals — no runtime allocation allowed)
// ---------------------------------------------------------------------------
__device__ float g_gates[(size_t)MROWS * NIH_PAD];   // also highway raw scratch
__device__ __nv_bfloat16 g_Ahi[(size_t)MROWS * KP];
__device__ __nv_bfloat16 g_Alo[(size_t)MROWS * KP];
__device__ __nv_bfloat16 g_Bhi[(size_t)NIH_PAD * KP];
__device__ __nv_bfloat16 g_Blo[(size_t)NIH_PAD * KP];
__device__ __nv_bfloat16 g_Whi[2 * G4P * HHP];
__device__ __nv_bfloat16 g_Wlo[2 * G4P * HHP];
__device__ __nv_bfloat16 g_hbf_hi[2][2 * BB * HHP];  // ping-pong h state (split hi)
__device__ __nv_bfloat16 g_hbf_lo[2][2 * BB * HHP];  // ping-pong h state (split lo)
__device__ float g_bias_sum[NIH];
__device__ float g_h[2 * BB * HH];
__device__ float g_c[2 * BB * HH];

__device__ __forceinline__ float sigm(float x) { return 1.0f / (1.0f + expf(-x)); }

// ---------------------------------------------------------------------------
// Big GEMM, double-buffered cp.async, wmma bf16 split precision.
// C[m0..+128, n0..+128] = A@B^T with split hi/lo (3 products), fp32 acc.
// Dynamic smem: 2 stages x 4 arrays x 128 x 40 bf16 = 81920 bytes.
// ---------------------------------------------------------------------------
#define STG 40960

__global__ void __launch_bounds__(256) gemm_wmma_kernel(
        const __nv_bfloat16* __restrict__ Ahi, const __nv_bfloat16* __restrict__ Alo,
        const __nv_bfloat16* __restrict__ Bhi, const __nv_bfloat16* __restrict__ Blo,
        float* __restrict__ C, int ldc) {
    extern __shared__ char dsm[];
    const int tid = threadIdx.x;
    const int wid = tid >> 5;
    const int wm = wid >> 1;        // 0..3 : 32-row slice
    const int wn = wid & 1;         // 0..1 : 64-col slice
    const size_t m0 = (size_t)blockIdx.x * 128;
    const size_t n0 = (size_t)blockIdx.y * 128;
    const int NKB = KP / 32;        // 26

    const __nv_bfloat16* gsrc[4] = {
        Ahi + m0 * KP, Alo + m0 * KP, Bhi + n0 * KP, Blo + n0 * KP };

    wmma::fragment<wmma::accumulator, 16, 16, 16, float> acc[2][4];
    #pragma unroll
    for (int i = 0; i < 2; i++)
        #pragma unroll
        for (int j = 0; j < 4; j++)
            wmma::fill_fragment(acc[i][j], 0.0f);

    // prime stage 0
    {
        char* st = dsm;
        #pragma unroll
        for (int a = 0; a < 4; a++) {
            const __nv_bfloat16* src = gsrc[a];
            #pragma unroll
            for (int r = 0; r < 2; r++) {
                int idx = tid + r * 256;
                int row = idx >> 2, seg = idx & 3;
                __pipeline_memcpy_async(st + a * 10240 + row * 80 + seg * 16,
                                        src + (size_t)row * KP + seg * 8, 16);
            }
        }
        __pipeline_commit();
    }

    for (int kb = 0; kb < NKB; kb++) {
        __pipeline_wait_prior(0);
        __syncthreads();
        if (kb + 1 < NKB) {
            char* st = dsm + ((kb + 1) & 1) * STG;
            #pragma unroll
            for (int a = 0; a < 4; a++) {
                const __nv_bfloat16* src = gsrc[a] + (kb + 1) * 32;
                #pragma unroll
                for (int r = 0; r < 2; r++) {
                    int idx = tid + r * 256;
                    int row = idx >> 2, seg = idx & 3;
                    __pipeline_memcpy_async(st + a * 10240 + row * 80 + seg * 16,
                                            src + (size_t)row * KP + seg * 8, 16);
                }
            }
            __pipeline_commit();
        }

        char* st = dsm + (kb & 1) * STG;
        typedef __nv_bfloat16 (*T40)[40];
        T40 sAh = (T40)st;
        T40 sAl = (T40)(st + 10240);
        T40 sBh = (T40)(st + 20480);
        T40 sBl = (T40)(st + 30720);

        #pragma unroll
        for (int ks = 0; ks < 2; ks++) {
            wmma::fragment<wmma::matrix_a, 16, 16, 16, __nv_bfloat16, wmma::row_major> ah[2], al[2];
            wmma::fragment<wmma::matrix_b, 16, 16, 16, __nv_bfloat16, wmma::col_major> bh[4], bl[4];
            #pragma unroll
            for (int i = 0; i < 2; i++) {
                wmma::load_matrix_sync(ah[i], &sAh[wm * 32 + i * 16][ks * 16], 40);
                wmma::load_matrix_sync(al[i], &sAl[wm * 32 + i * 16][ks * 16], 40);
            }
            #pragma unroll
            for (int j = 0; j < 4; j++) {
                wmma::load_matrix_sync(bh[j], &sBh[wn * 64 + j * 16][ks * 16], 40);
                wmma::load_matrix_sync(bl[j], &sBl[wn * 64 + j * 16][ks * 16], 40);
            }
            #pragma unroll
            for (int i = 0; i < 2; i++)
                #pragma unroll
                for (int j = 0; j < 4; j++) {
                    wmma::mma_sync(acc[i][j], ah[i], bh[j], acc[i][j]);
                    wmma::mma_sync(acc[i][j], ah[i], bl[j], acc[i][j]);
                    wmma::mma_sync(acc[i][j], al[i], bh[j], acc[i][j]);
                }
        }
        __syncthreads();
    }

    #pragma unroll
    for (int i = 0; i < 2; i++)
        #pragma unroll
        for (int j = 0; j < 4; j++)
            wmma::store_matrix_sync(&C[(m0 + wm * 32 + i * 16) * ldc + n0 + wn * 64 + j * 16],
                                    acc[i][j], ldc, wmma::mem_row_major);
}

// ---------------------------------------------------------------------------
// Fused recurrent step: gate-quad GEMM + LSTM cell in one kernel.
// grid (2, 75, 2) = (m-tile of 64, hh-tile of 8, dir). CTA = 128 thr (4 warps).
// CTA computes 64 rows x 32 gate-cols (i,f,g,o x 8 hh), K=HHP, split bf16,
// then applies the cell elementwise and writes c, h, split-h (ping-pong), ctx.
// ---------------------------------------------------------------------------
#define SSTG 15360

__global__ void __launch_bounds__(128) step_fused_kernel(float* __restrict__ context, int t) {
    __shared__ char sm[2 * SSTG];
    const int tid = threadIdx.x;
    const int wid = tid >> 5;             // 0..3 : 16-row slice
    const int mt = blockIdx.x;            // 0..1
    const int hh0 = blockIdx.y * 8;       // 0..592
    const int d = blockIdx.z;
    const int cur = t & 1, nxt = cur ^ 1;

    const __nv_bfloat16* Ahi = g_hbf_hi[cur] + (size_t)(d * BB + mt * 64) * HHP;
    const __nv_bfloat16* Alo = g_hbf_lo[cur] + (size_t)(d * BB + mt * 64) * HHP;
    const __nv_bfloat16* Whi = g_Whi + (size_t)d * G4P * HHP;
    const __nv_bfloat16* Wlo = g_Wlo + (size_t)d * G4P * HHP;

    // B gather row for this thread (32 rows: gate-major, 8 hh each)
    const int brow = tid >> 2;            // 0..31
    const int bseg = tid & 3;
    const size_t bsrc = (size_t)((brow >> 3) * HH + hh0 + (brow & 7)) * HHP;

    wmma::fragment<wmma::accumulator, 16, 16, 16, float> acc[2];
    wmma::fill_fragment(acc[0], 0.0f);
    wmma::fill_fragment(acc[1], 0.0f);

    const int NKB = HHP / 32;             // 19

    // prime stage 0
    {
        char* st = sm;
        #pragma unroll
        for (int r = 0; r < 2; r++) {
            int idx = tid + r * 128;
            int row = idx >> 2, seg = idx & 3;
            __pipeline_memcpy_async(st + row * 80 + seg * 16,
                                    Ahi + (size_t)row * HHP + seg * 8, 16);
            __pipeline_memcpy_async(st + 5120 + row * 80 + seg * 16,
                                    Alo + (size_t)row * HHP + seg * 8, 16);
        }
        __pipeline_memcpy_async(st + 10240 + brow * 80 + bseg * 16, Whi + bsrc + bseg * 8, 16);
        __pipeline_memcpy_async(st + 12800 + brow * 80 + bseg * 16, Wlo + bsrc + bseg * 8, 16);
        __pipeline_commit();
    }

    for (int kb = 0; kb < NKB; kb++) {
        __pipeline_wait_prior(0);
        __syncthreads();
        if (kb + 1 < NKB) {
            char* st = sm + ((kb + 1) & 1) * SSTG;
            int ko = (kb + 1) * 32;
            #pragma unroll
            for (int r = 0; r < 2; r++) {
                int idx = tid + r * 128;
                int row = idx >> 2, seg = idx & 3;
                __pipeline_memcpy_async(st + row * 80 + seg * 16,
                                        Ahi + (size_t)row * HHP + ko + seg * 8, 16);
                __pipeline_memcpy_async(st + 5120 + row * 80 + seg * 16,
                                        Alo + (size_t)row * HHP + ko + seg * 8, 16);
            }
            __pipeline_memcpy_async(st + 10240 + brow * 80 + bseg * 16,
                                    Whi + bsrc + ko + bseg * 8, 16);
            __pipeline_memcpy_async(st + 12800 + brow * 80 + bseg * 16,
                                    Wlo + bsrc + ko + bseg * 8, 16);
            __pipeline_commit();
        }

        char* st = sm + (kb & 1) * SSTG;
        typedef __nv_bfloat16 (*T40)[40];
        T40 sAh = (T40)st;
        T40 sAl = (T40)(st + 5120);
        T40 sBh = (T40)(st + 10240);
        T40 sBl = (T40)(st + 12800);

        #pragma unroll
        for (int ks = 0; ks < 2; ks++) {
            wmma::fragment<wmma::matrix_a, 16, 16, 16, __nv_bfloat16, wmma::row_major> ah, al;
            wmma::fragment<wmma::matrix_b, 16, 16, 16, __nv_bfloat16, wmma::col_major> bh[2], bl[2];
            wmma::load_matrix_sync(ah, &sAh[wid * 16][ks * 16], 40);
            wmma::load_matrix_sync(al, &sAl[wid * 16][ks * 16], 40);
            #pragma unroll
            for (int j = 0; j < 2; j++) {
                wmma::load_matrix_sync(bh[j], &sBh[j * 16][ks * 16], 40);
                wmma::load_matrix_sync(bl[j], &sBl[j * 16][ks * 16], 40);
            }
            #pragma unroll
            for (int j = 0; j < 2; j++) {
                wmma::mma_sync(acc[j], ah, bh[j], acc[j]);
                wmma::mma_sync(acc[j], ah, bl[j], acc[j]);
                wmma::mma_sync(acc[j], al, bh[j], acc[j]);
            }
        }
        __syncthreads();
    }

    // stage gates through smem (alias stage 0; all compute done)
    float (*sg)[32] = (float(*)[32])sm;
    wmma::store_matrix_sync(&sg[wid * 16][0], acc[0], 32, wmma::mem_row_major);
    wmma::store_matrix_sync(&sg[wid * 16][16], acc[1], 32, wmma::mem_row_major);
    __syncthreads();

    // LSTM cell: 512 elements (64 rows x 8 hh)
    #pragma unroll
    for (int q = 0; q < 4; q++) {
        int e = tid + q * 128;
        int bl_ = e >> 3, hl = e & 7;
        int b = mt * 64 + bl_;
        int hh = hh0 + hl;
        size_t gx = ((size_t)b * SS + t) * NIH_PAD + d * G4;
        int bi = d * G4;
        float gi = sg[bl_][hl]      + g_gates[gx + hh]          + g_bias_sum[bi + hh];
        float gf = sg[bl_][8 + hl]  + g_gates[gx + HH + hh]     + g_bias_sum[bi + HH + hh];
        float gg = sg[bl_][16 + hl] + g_gates[gx + 2 * HH + hh] + g_bias_sum[bi + 2 * HH + hh];
        float go = sg[bl_][24 + hl] + g_gates[gx + 3 * HH + hh] + g_bias_sum[bi + 3 * HH + hh];
        size_t ci = (size_t)(d * BB + b) * HH + hh;
        float cold = g_c[ci];
        float cn = sigm(gf) * cold + sigm(gi) * tanhf(gg);
        float hn = sigm(go) * tanhf(cn);
        g_c[ci] = cn;
        g_h[ci] = hn;
        size_t hb = (size_t)(d * BB + b) * HHP + hh;
        __nv_bfloat16 hi = __float2bfloat16(hn);
        g_hbf_hi[nxt][hb] = hi;
        g_hbf_lo[nxt][hb] = __float2bfloat16(hn - __bfloat162float(hi));
        context[(size_t)t * OUT_BLK + (size_t)b * CTX_STRIDE + d * HH + hh] = hn;
    }
}

// ---------------------------------------------------------------------------
// Conversions / elementwise
// ---------------------------------------------------------------------------
__global__ void init_kernel(const float* __restrict__ h0, const float* __restrict__ c0,
                            const float* __restrict__ b_ih, const float* __restrict__ b_hh) {
    int idx = blockIdx.x * blockDim.x + threadIdx.x;
    if (idx < 2 * BB * HH) { g_h[idx] = h0[idx]; g_c[idx] = c0[idx]; }
    if (idx < NIH) g_bias_sum[idx] = b_ih[idx] + b_hh[idx];
    if (idx < 2 * BB * HHP) {
        int hh = idx % HHP;
        int db = idx / HHP;
        float v = (hh < HH) ? h0[db * HH + hh] : 0.0f;
        __nv_bfloat16 hi = __float2bfloat16(v);
        __nv_bfloat16 lo = __float2bfloat16(v - __bfloat162float(hi));
        g_hbf_hi[0][idx] = hi; g_hbf_lo[0][idx] = lo;
        g_hbf_hi[1][idx] = hi; g_hbf_lo[1][idx] = lo;   // padding must stay zero in both
    }
}

__global__ void convA_kernel(const float* __restrict__ src) {
    int idx = blockIdx.x * blockDim.x + threadIdx.x;
    if (idx >= MROWS * KP) return;
    int col = idx % KP, row = idx / KP;
    float v = (col < EE) ? src[(size_t)row * EE + col] : 0.0f;
    __nv_bfloat16 hi = __float2bfloat16(v);
    g_Ahi[idx] = hi;
    g_Alo[idx] = __float2bfloat16(v - __bfloat162float(hi));
}

__global__ void convW_kernel(const float* __restrict__ src, int Nreal, int Npad) {
    int idx = blockIdx.x * blockDim.x + threadIdx.x;
    if (idx >= Npad * KP) return;
    int col = idx % KP, row = idx / KP;
    float v = (row < Nreal && col < EE) ? src[(size_t)row * EE + col] : 0.0f;
    __nv_bfloat16 hi = __float2bfloat16(v);
    g_Bhi[idx] = hi;
    g_Blo[idx] = __float2bfloat16(v - __bfloat162float(hi));
}

__global__ void convWhh_kernel(const float* __restrict__ W) {
    int idx = blockIdx.x * blockDim.x + threadIdx.x;
    if (idx >= 2 * G4P * HHP) return;
    int col = idx % HHP;
    int rowd = idx / HHP;
    int row = rowd % G4P;
    int d = rowd / G4P;
    float v = (row < G4 && col < HH) ? W[((size_t)d * G4 + row) * HH + col] : 0.0f;
    __nv_bfloat16 hi = __float2bfloat16(v);
    g_Whi[idx] = hi;
    g_Wlo[idx] = __float2bfloat16(v - __bfloat162float(hi));
}

__global__ void combine_kernel(const float* __restrict__ rawG, const float* __restrict__ rawN,
                               const float* __restrict__ rawL,
                               const float* __restrict__ bg, const float* __restrict__ bn,
                               const float* __restrict__ bl) {
    int idx = blockIdx.x * blockDim.x + threadIdx.x;
    if (idx >= MROWS * KP) return;
    int col = idx % KP, row = idx / KP;
    float y = 0.0f;
    if (col < EE) {
        size_t r = (size_t)row * NHW_PAD + col;
        float gate = sigm(rawG[r] + bg[col]);
        float nl   = fmaxf(rawN[r] + bn[col], 0.0f);
        float ln   = rawL[r] + bl[col];
        y = gate * nl + (1.0f - gate) * ln;
    }
    __nv_bfloat16 hi = __float2bfloat16(y);
    g_Ahi[idx] = hi;
    g_Alo[idx] = __float2bfloat16(y - __bfloat162float(hi));
}

__global__ void finalize_kernel(float* __restrict__ out) {
    int idx = blockIdx.x * blockDim.x + threadIdx.x;
    if (idx >= OUT_BLK) return;
    const float* ctx_last = out + 4L * OUT_BLK + (long)(SS - 1) * OUT_BLK;
    float v = ctx_last[idx];
    out[idx] = v;
    out[OUT_BLK + idx] = v;
    out[2L * OUT_BLK + idx] = g_h[idx];
    out[3L * OUT_BLK + idx] = g_c[idx];
}

// ---------------------------------------------------------------------------
extern "C" void kernel_launch(void* const* d_in, const int* in_sizes, int n_in,
                              void* d_out, int out_size) {
    const float* x      = (const float*)d_in[0];
    const float* h0     = (const float*)d_in[1];
    const float* c0     = (const float*)d_in[2];
    const float* hw_Wg  = (const float*)d_in[3];
    const float* hw_bg  = (const float*)d_in[4];
    const float* hw_Wn  = (const float*)d_in[5];
    const float* hw_bn  = (const float*)d_in[6];
    const float* hw_Wl  = (const float*)d_in[7];
    const float* hw_bl  = (const float*)d_in[8];
    const float* W_ih   = (const float*)d_in[9];
    const float* W_hh   = (const float*)d_in[10];
    const float* b_ih   = (const float*)d_in[11];
    const float* b_hh   = (const float*)d_in[12];
    float* out = (float*)d_out;

    static bool attr_set = false;
    if (!attr_set) {
        cudaFuncSetAttribute(gemm_wmma_kernel,
                             cudaFuncAttributeMaxDynamicSharedMemorySize, 2 * STG);
        attr_set = true;
    }

    float *p_gates;
    __nv_bfloat16 *p_Ahi, *p_Alo, *p_Bhi, *p_Blo;
    cudaGetSymbolAddress((void**)&p_gates, g_gates);
    cudaGetSymbolAddress((void**)&p_Ahi, g_Ahi);
    cudaGetSymbolAddress((void**)&p_Alo, g_Alo);
    cudaGetSymbolAddress((void**)&p_Bhi, g_Bhi);
    cudaGetSymbolAddress((void**)&p_Blo, g_Blo);

    init_kernel<<<(2 * BB * HHP + 255) / 256, 256>>>(h0, c0, b_ih, b_hh);

    // W_hh split conversion (independent, do early)
    convWhh_kernel<<<(2 * G4P * HHP + 255) / 256, 256>>>(W_hh);

    // x -> split bf16 activations
    convA_kernel<<<(MROWS * KP + 255) / 256, 256>>>(x);

    // Highway layers via wmma (raw G/N/L into g_gates scratch, stride NHW_PAD)
    float* raw[3] = { p_gates,
                      p_gates + (size_t)MROWS * NHW_PAD,
                      p_gates + 2 * (size_t)MROWS * NHW_PAD };
    const float* Ws[3] = { hw_Wg, hw_Wn, hw_Wl };
    dim3 gHW(MROWS / 128, NHW_PAD / 128);  // 256 x 7
    for (int l = 0; l < 2; l++) {
        for (int w = 0; w < 3; w++) {
            convW_kernel<<<(NHW_PAD * KP + 255) / 256, 256>>>(Ws[w] + (size_t)l * EE * EE, EE, NHW_PAD);
            gemm_wmma_kernel<<<gHW, 256, 2 * STG>>>(p_Ahi, p_Alo, p_Bhi, p_Blo, raw[w], NHW_PAD);
        }
        combine_kernel<<<(MROWS * KP + 255) / 256, 256>>>(
            raw[0], raw[1], raw[2],
            hw_bg + l * EE, hw_bn + l * EE, hw_bl + l * EE);
    }

    // Input-gate precompute: (32768 x 4864) via wmma (raw, bias folded into cell)
    convW_kernel<<<(NIH_PAD * KP + 255) / 256, 256>>>(W_ih, NIH, NIH_PAD);
    dim3 gGX(MROWS / 128, NIH_PAD / 128);  // 256 x 38
    gemm_wmma_kernel<<<gGX, 256, 2 * STG>>>(p_Ahi, p_Alo, p_Bhi, p_Blo, p_gates, NIH_PAD);

    // Sequential recurrence: one fused kernel per step
    dim3 gST(2, HH / 8, 2);  // (m-tile, hh-tile, dir) = 300 CTAs
    float* context = out + 4L * OUT_BLK;
    for (int t = 0; t < SS; t++) {
        step_fused_kernel<<<gST, 128>>>(context, t);
    }

    finalize_kernel<<<(OUT_BLK + 255) / 256, 256>>>(out);
}